// round 16
// baseline (speedup 1.0000x reference)
#include <cuda_runtime.h>
#include <cstdint>
#include <math.h>

#define FULLM 0xFFFFFFFFu
#define TPB   256
#define WPB   (TPB / 32)           // 8 warps per block
#define TROWS 24                   // rows per tile (geo: exactly 2 batches)
#define WTILE 3168                 // bytes per warp tile (24 rows * 132 B)
#define NBUF  2
#define WSLICE (NBUF * WTILE)      // 6336 B per warp
#define GRID  592                  // 4 blocks/SM * 148 SMs (smem 4*50.7KB=203KB)

struct ContTab { float v[13]; };

__constant__ float CW_C[12] = {1.0f, 0.8f, 0.64f, 0.512f, 0.4096f, 0.32768f,
                               0.262144f, 0.2097152f, 0.16777216f, 0.134217728f,
                               0.1073741824f, 0.08589934592f};

// 0=mask_ce_sum 1=valid_cnt 2=correct_sum 3=error_sum 4=prefix_sum
__device__ double   g_acc[5];
__device__ unsigned g_done;

__device__ __forceinline__ double warp_dsum(double v) {
    #pragma unroll
    for (int d = 16; d; d >>= 1) v += __shfl_xor_sync(FULLM, v, d);
    return v;
}

__device__ __forceinline__ void mbar_init(unsigned int mbar) {
    asm volatile("mbarrier.init.shared.b64 [%0], 1;" :: "r"(mbar) : "memory");
}
__device__ __forceinline__ void mbar_expect_tx(unsigned int mbar, unsigned int bytes) {
    asm volatile("mbarrier.arrive.expect_tx.shared.b64 _, [%0], %1;"
                 :: "r"(mbar), "r"(bytes) : "memory");
}
__device__ __forceinline__ void bulk_g2s(unsigned int dst, const void* src,
                                         unsigned int bytes, unsigned int mbar) {
    asm volatile("cp.async.bulk.shared::cta.global.mbarrier::complete_tx::bytes "
                 "[%0], [%1], %2, [%3];"
                 :: "r"(dst), "l"(src), "r"(bytes), "r"(mbar) : "memory");
}
__device__ __forceinline__ void mbar_wait(unsigned int mbar, unsigned int parity) {
    asm volatile(
        "{\n\t.reg .pred P;\n\t"
        "W%=:\n\t"
        "mbarrier.try_wait.parity.acquire.cta.shared::cta.b64 P, [%0], %1, 0x989680;\n\t"
        "@P bra D%=;\n\t"
        "bra W%=;\n\t"
        "D%=:\n\t}"
        :: "r"(mbar), "r"(parity) : "memory");
}
__device__ __forceinline__ void fence_async() {
    asm volatile("fence.proxy.async.shared::cta;" ::: "memory");
}

__global__ __launch_bounds__(TPB, 4) void fused_kernel(
    const float* __restrict__ geo, const int* __restrict__ pos,
    const float* __restrict__ mgo, const int* __restrict__ gt,
    const float* __restrict__ aux, const float* __restrict__ tok,
    const float* __restrict__ sigma, float* __restrict__ out,
    int B, long nrows, long NTg, long NT, ContTab cont)
{
    // Per-warp private double-buffered slices, filled by cp.async.bulk with
    // per-warp-per-buffer mbarrier completion. No block barriers in the main
    // loop; 32 independent pipelines/SM.
    extern __shared__ char shm[];
    __shared__ double shred[WPB * 5];
    __shared__ alignas(8) unsigned long long mbar_s[WPB][NBUF];

    const int tid  = threadIdx.x;
    const int lane = tid & 31;
    const int w    = tid >> 5;
    const unsigned int slice =
        (unsigned int)__cvta_generic_to_shared(shm) + w * WSLICE;
    const unsigned int mb0 =
        (unsigned int)__cvta_generic_to_shared(&mbar_s[w][0]);
    const unsigned int mb1 = mb0 + 8;

    if (lane == 0) { mbar_init(mb0); mbar_init(mb1); }
    __syncthreads();
    fence_async();          // init visible to the async proxy before first bulk

    // Geo: lane l (l<24) owns row l of a 2-batch tile; j = l%12, batch = l/12.
    // Row stride 132 B -> smem bank of elem i for lane l is (l+i)%32: conflict-free.
    const int  jj    = (lane < 12) ? lane : lane - 12;
    const int  batch = (lane < 12) ? 0 : 1;
    const float cwj  = CW_C[jj];
    const float cwj1 = cwj + 1.0f;

    float accS = 0.f, accV = 0.f, accC = 0.f, accE = 0.f, accP = 0.f;

    // Fill tile u into buffer bufidx via one bulk copy (lane 0). Tail bytes
    // (<16, only a ragged last mask tile) copied synchronously by lanes.
    auto load_tile = [&](long u, int bufidx) {
        const unsigned int dst = slice + bufidx * WTILE;
        const unsigned int mb  = bufidx ? mb1 : mb0;
        const char* src;
        int bytes;
        if (u < NTg) {
            const long b0 = u * 2;
            const int  nb = (int)min(2L, (long)B - b0);
            src   = (const char*)(geo + b0 * 396);
            bytes = nb * 1584;                        // always % 16 == 0
        } else {
            const long r0 = (u - NTg) * TROWS;
            const int  nr = (int)min((long)TROWS, nrows - r0);
            src   = (const char*)(mgo + r0 * 33);
            bytes = nr * 132;                         // % 16 == 0 unless ragged
        }
        const unsigned int bb = (unsigned int)(bytes & ~15);   // bulk part
        fence_async();       // order prior generic smem reads before async write
        if (lane == 0) {
            mbar_expect_tx(mb, bb);
            bulk_g2s(dst, src, bb, mb);
        }
        const int tf = (bytes & 15) >> 2;             // 0..3 tail floats
        if (lane < tf) {
            float v = *(const float*)(src + bb + lane * 4);
            *(float*)(shm + (size_t)w * WSLICE + (size_t)bufidx * WTILE
                      + bb + lane * 4) = v;
        }
    };

    const long gw = (long)blockIdx.x * WPB + w;      // global warp id
    const long nw = (long)gridDim.x * WPB;           // total warps

    if (gw < NT) load_tile(gw, 0);

    int cur = 0;
    int ph0 = 0, ph1 = 0;                            // parity per buffer
    for (long u = gw; u < NT; u += nw) {
        const long un = u + nw;
        if (un < NT) load_tile(un, cur ^ 1);

        // Hoisted index/target loads for tile u (hide under the mbarrier wait).
        int  pre = -100;
        int  nb = 0, nr = 0;
        long b0 = 0, r0 = 0;
        if (u < NTg) {
            b0 = u * 2;
            nb = (int)min(2L, (long)B - b0);
            if (lane < nb * 12) pre = pos[(b0 + batch) * 13 + jj + 1];
        } else {
            r0 = (u - NTg) * TROWS;
            nr = (int)min((long)TROWS, nrows - r0);
            if (lane < nr) pre = gt[r0 + lane];
        }

        if (cur == 0) { mbar_wait(mb0, ph0); ph0 ^= 1; }
        else          { mbar_wait(mb1, ph1); ph1 ^= 1; }
        __syncwarp();                                // all lanes see the tile

        const float* buf = (const float*)(shm + (size_t)w * WSLICE
                                              + (size_t)cur * WTILE);
        if (u < NTg) {
            // ------------- geo tile: 2 batches x 12 positions -------------
            const bool act = lane < nb * 12;
            float cel = 0.f;
            bool  cor = false;
            if (act) {
                const float* p = buf + lane * 33;
                float m0 = -1e30f, m1 = -1e30f, m2 = -1e30f, m3 = -1e30f;
                float s0 = 0.f, s1 = 0.f, s2 = 0.f, s3 = 0.f;
                #pragma unroll
                for (int i = 0; i < 32; i += 4) {
                    float a = p[i], b = p[i+1], c = p[i+2], d = p[i+3];
                    m0 = fmaxf(m0, a); m1 = fmaxf(m1, b);
                    m2 = fmaxf(m2, c); m3 = fmaxf(m3, d);
                    s0 += __expf(a); s1 += __expf(b);
                    s2 += __expf(c); s3 += __expf(d);
                }
                const float e32 = p[32];
                const float m = fmaxf(fmaxf(fmaxf(m0, m1), fmaxf(m2, m3)), e32);
                const float s = (s0 + s1) + (s2 + s3) + __expf(e32);
                const float pt = p[pre];             // pre in 0..32 when act
                cor = (pt == m);       // ties measure-zero for random logits
                cel = (pre == 32) ? 0.f : (__logf(s) - pt);
            }
            const unsigned bal = __ballot_sync(FULLM, cor);
            if (act) {
                const unsigned m12 = (bal >> (batch * 12)) & 0xFFFu;
                const int mi = (m12 == 0xFFFu) ? 0 : (__ffs((int)~m12) - 1);
                const bool ok = (m12 >> jj) & 1u;
                accC += ok ? cel * cwj  : 0.f;
                accE += ok ? 0.f        : cel * cwj1;
                accP += (jj < mi) ? cel * cont.v[mi] : 0.f;
            }
        } else {
            // ------------- mask tile: TROWS rows of 33 -------------
            if (lane < nr) {
                const float* p = buf + lane * 33;
                float s0 = 0.f, s1 = 0.f, s2 = 0.f, s3 = 0.f;
                #pragma unroll
                for (int i = 0; i < 32; i += 4) {
                    s0 += __expf(p[i]);   s1 += __expf(p[i+1]);
                    s2 += __expf(p[i+2]); s3 += __expf(p[i+3]);
                }
                const float s = (s0 + s1) + (s2 + s3) + __expf(p[32]);
                const int tc = min(max(pre, 0), 32);
                if (pre != -100) {
                    accS += __logf(s) - p[tc];
                    accV += 1.f;
                }
            }
        }
        __syncwarp();       // all lanes done reading buf before it is refilled
        cur ^= 1;
    }
    // Every issued bulk was awaited (prefetch only for tiles that get consumed).

    // ---------------- block reduction -> global atomics ----------------
    double d0 = warp_dsum((double)accS);
    double d1 = warp_dsum((double)accV);
    double d2 = warp_dsum((double)accC);
    double d3 = warp_dsum((double)accE);
    double d4 = warp_dsum((double)accP);
    if (lane == 0) {
        shred[w] = d0; shred[WPB + w] = d1; shred[2*WPB + w] = d2;
        shred[3*WPB + w] = d3; shred[4*WPB + w] = d4;
    }
    __syncthreads();
    if (tid == 0) {
        double a0 = 0, a1 = 0, a2 = 0, a3 = 0, a4 = 0;
        #pragma unroll
        for (int i = 0; i < WPB; i++) {
            a0 += shred[i];          a1 += shred[WPB + i];
            a2 += shred[2*WPB + i];  a3 += shred[3*WPB + i];
            a4 += shred[4*WPB + i];
        }
        atomicAdd(&g_acc[0], a0);
        atomicAdd(&g_acc[1], a1);
        atomicAdd(&g_acc[2], a2);
        atomicAdd(&g_acc[3], a3);
        atomicAdd(&g_acc[4], a4);
        __threadfence();
        unsigned done = atomicAdd(&g_done, 1u);
        if (done == gridDim.x - 1) {
            // last block: read-and-zero (deterministic across graph replays)
            double s0 = __longlong_as_double(atomicExch((unsigned long long*)&g_acc[0], 0ull));
            double s1 = __longlong_as_double(atomicExch((unsigned long long*)&g_acc[1], 0ull));
            double s2 = __longlong_as_double(atomicExch((unsigned long long*)&g_acc[2], 0ull));
            double s3 = __longlong_as_double(atomicExch((unsigned long long*)&g_acc[3], 0ull));
            double s4 = __longlong_as_double(atomicExch((unsigned long long*)&g_acc[4], 0ull));
            atomicExch(&g_done, 0u);

            const double den = (double)B * 12.0;
            double mask_loss = s0 / fmax(s1, 1.0);
            double pl = s4 / den, cl = s2 / den, el = s3 / den;
            double gl = pl + cl + el;
            double L[4] = { gl, mask_loss, (double)aux[0], (double)tok[0] };
            double wsum = 0.0, prod = 1.0;
            #pragma unroll
            for (int i = 0; i < 4; i++) {
                double sg = (double)sigma[i];
                wsum += 0.5 * L[i] / (sg * sg);
                prod *= sg;
            }
            wsum += log(prod);
            out[0] = (float)wsum;
            out[1] = (float)pl;
            out[2] = (float)cl;
            out[3] = (float)el;
            out[4] = (float)mask_loss;
        }
    }
}

extern "C" void kernel_launch(void* const* d_in, const int* in_sizes, int n_in,
                              void* d_out, int out_size) {
    (void)n_in; (void)out_size;
    const float* geo   = (const float*)d_in[0];   // (B, 12, 33) f32
    const float* mgo   = (const float*)d_in[1];   // (B, 13, 33) f32
    const int*   pos   = (const int*)  d_in[2];   // (B, 13) i32
    const int*   gt    = (const int*)  d_in[3];   // (B, 13) i32
    const float* aux   = (const float*)d_in[4];
    const float* tok   = (const float*)d_in[5];
    const float* sigma = (const float*)d_in[6];
    float* out = (float*)d_out;

    const int  B     = (int)((long)in_sizes[0] / 396);
    const long nrows = (long)in_sizes[1] / 33;    // B * 13
    const long NTg   = ((long)B + 1) / 2;         // geo tiles (2 batches each)
    const long NTm   = (nrows + TROWS - 1) / TROWS; // mask tiles (24 rows each)
    const long NT    = NTg + NTm;

    // CONT_REWARDS closed-form geometric series == reference's Riemann sum
    ContTab cont;
    cont.v[0] = 0.0f;
    for (int k = 1; k <= 12; k++) {
        double b = (double)k;
        double r = pow(0.8, b / 1999.0);
        double integral = (b / 2000.0) * (1.0 - pow(r, 2000.0)) / (1.0 - r);
        cont.v[k] = (float)(1.0 / integral);
    }

    const int dyn_smem = WPB * WSLICE;            // 8 warps * 6336 B = 50688 B
    cudaFuncSetAttribute(fused_kernel,
                         cudaFuncAttributeMaxDynamicSharedMemorySize, dyn_smem);
    fused_kernel<<<GRID, TPB, dyn_smem>>>(geo, pos, mgo, gt, aux, tok, sigma, out,
                                          B, nrows, NTg, NT, cont);
}

// round 17
// speedup vs baseline: 1.0019x; 1.0019x over previous
#include <cuda_runtime.h>
#include <cstdint>
#include <math.h>

#define FULLM 0xFFFFFFFFu
#define TPB   256
#define WPB   (TPB / 32)           // 8 warps per block
#define BUFB  33792                // block buffer bytes (max tile: 256 mask rows)
#define NBUF  2
#define GRID  444                  // 3 blocks/SM * 148 SMs (smem 3*68KB=204KB)

#define GEO_BATCHES 16             // batches per geo block tile (16*1584=25344 B)
#define MASK_ROWS   256            // rows per mask block tile  (256*132=33792 B)

struct ContTab { float v[13]; };

__constant__ float CW_C[12] = {1.0f, 0.8f, 0.64f, 0.512f, 0.4096f, 0.32768f,
                               0.262144f, 0.2097152f, 0.16777216f, 0.134217728f,
                               0.1073741824f, 0.08589934592f};

// 0=mask_ce_sum 1=valid_cnt 2=correct_sum 3=error_sum 4=prefix_sum
__device__ double   g_acc[5];
__device__ unsigned g_done;

__device__ __forceinline__ double warp_dsum(double v) {
    #pragma unroll
    for (int d = 16; d; d >>= 1) v += __shfl_xor_sync(FULLM, v, d);
    return v;
}

__device__ __forceinline__ void mbar_init(unsigned int mbar, unsigned int cnt) {
    asm volatile("mbarrier.init.shared.b64 [%0], %1;" :: "r"(mbar), "r"(cnt) : "memory");
}
__device__ __forceinline__ void mbar_expect_tx(unsigned int mbar, unsigned int bytes) {
    asm volatile("mbarrier.arrive.expect_tx.shared.b64 _, [%0], %1;"
                 :: "r"(mbar), "r"(bytes) : "memory");
}
__device__ __forceinline__ void mbar_arrive(unsigned int mbar) {
    asm volatile("mbarrier.arrive.shared.b64 _, [%0];" :: "r"(mbar) : "memory");
}
__device__ __forceinline__ void bulk_g2s(unsigned int dst, const void* src,
                                         unsigned int bytes, unsigned int mbar) {
    asm volatile("cp.async.bulk.shared::cta.global.mbarrier::complete_tx::bytes "
                 "[%0], [%1], %2, [%3];"
                 :: "r"(dst), "l"(src), "r"(bytes), "r"(mbar) : "memory");
}
__device__ __forceinline__ void mbar_wait(unsigned int mbar, unsigned int parity) {
    asm volatile(
        "{\n\t.reg .pred P;\n\t"
        "W%=:\n\t"
        "mbarrier.try_wait.parity.acquire.cta.shared::cta.b64 P, [%0], %1, 0x989680;\n\t"
        "@P bra D%=;\n\t"
        "bra W%=;\n\t"
        "D%=:\n\t}"
        :: "r"(mbar), "r"(parity) : "memory");
}
__device__ __forceinline__ void fence_async() {
    asm volatile("fence.proxy.async.shared::cta;" ::: "memory");
}

__global__ __launch_bounds__(TPB, 3) void fused_kernel(
    const float* __restrict__ geo, const int* __restrict__ pos,
    const float* __restrict__ mgo, const int* __restrict__ gt,
    const float* __restrict__ aux, const float* __restrict__ tok,
    const float* __restrict__ sigma, float* __restrict__ out,
    int B, long nrows, long NTg, long NT, ContTab cont)
{
    // BLOCK-level double-buffered bulk fills (one 25-34KB TMA request per tile,
    // 8x larger than per-warp fills) + warp-sliced consumption. No __syncthreads
    // in the loop: consumers wait `full` parity; arrive 8-count `empty`;
    // producer (tid 0) waits `empty` before refilling.
    extern __shared__ char shm[];
    __shared__ double shred[WPB * 5];
    __shared__ alignas(8) unsigned long long mb_full[NBUF], mb_empty[NBUF];

    const int tid  = threadIdx.x;
    const int lane = tid & 31;
    const int w    = tid >> 5;
    const unsigned int shb  = (unsigned int)__cvta_generic_to_shared(shm);
    const unsigned int mbF0 = (unsigned int)__cvta_generic_to_shared(&mb_full[0]);
    const unsigned int mbE0 = (unsigned int)__cvta_generic_to_shared(&mb_empty[0]);

    if (tid == 0) {
        mbar_init(mbF0, 1);     mbar_init(mbF0 + 8, 1);
        mbar_init(mbE0, WPB);   mbar_init(mbE0 + 8, WPB);
    }
    __syncthreads();
    fence_async();

    // Geo: warp w owns batches 2w, 2w+1 of the 16-batch tile; lane l (<24)
    // owns row l of the warp slice (j = l%12, batch = 2w + l/12).
    // Slice stride 3168 B, row stride 132 B -> banks (l+i)%32: conflict-free.
    const int  jj    = (lane < 12) ? lane : lane - 12;
    const int  bsub  = (lane < 12) ? 0 : 1;
    const float cwj  = CW_C[jj];
    const float cwj1 = cwj + 1.0f;

    float accS = 0.f, accV = 0.f, accC = 0.f, accE = 0.f, accP = 0.f;

    const long t0 = blockIdx.x;
    const long g  = gridDim.x;

    // Producer fill (tid 0 only): one bulk per block tile.
    auto fill = [&](long u, int b) {
        const unsigned int dst = shb + b * BUFB;
        const char* src;
        int bytes;
        if (u < NTg) {
            const long b0 = u * GEO_BATCHES;
            const int  nb = (int)min((long)GEO_BATCHES, (long)B - b0);
            src   = (const char*)(geo + b0 * 396);
            bytes = nb * 1584;                       // % 16 == 0 always
        } else {
            const long r0 = (u - NTg) * MASK_ROWS;
            const int  nr = (int)min((long)MASK_ROWS, nrows - r0);
            src   = (const char*)(mgo + r0 * 33);
            bytes = nr * 132;                        // % 16 == 0 unless ragged
        }
        const unsigned int bb = (unsigned int)(bytes & ~15);
        // ragged tail (absent at these shapes): generic stores before the
        // release-arrive of expect_tx -> visible to consumers' acquire.
        for (int c = bb; c < bytes; c += 4)
            *(float*)(shm + b * BUFB + c) = *(const float*)(src + c);
        fence_async();
        mbar_expect_tx(mbF0 + b * 8, bb);
        bulk_g2s(dst, src, bb, mbF0 + b * 8);
    };

    if (tid == 0) {
        if (t0 < NT)     fill(t0, 0);
        if (t0 + g < NT) fill(t0 + g, 1);
    }

    int it = 0;
    for (long u = t0; u < NT; u += g, it++) {
        const int b = it & 1;
        const unsigned int par = (unsigned)(it >> 1) & 1u;

        // Hoisted index/target loads (hide under the full-wait).
        int pre = -100;
        int nb = 0, nr = 0;
        if (u < NTg) {
            const long b0 = u * GEO_BATCHES;
            nb = (int)min((long)GEO_BATCHES, (long)B - b0);
            const int myb = 2 * w + bsub;            // batch within tile
            if (lane < 24 && myb < nb)
                pre = pos[(b0 + myb) * 13 + jj + 1];
        } else {
            const long r0 = (u - NTg) * MASK_ROWS;
            nr = (int)min((long)MASK_ROWS, nrows - r0);
            if (w * 32 + lane < nr)
                pre = gt[r0 + w * 32 + lane];
        }

        mbar_wait(mbF0 + b * 8, par);                // tile data visible (acquire)

        if (u < NTg) {
            // ---- geo: my slice = 2 batches x 12 rows at byte off w*3168 ----
            const float* p0 = (const float*)(shm + b * BUFB + w * 3168);
            const int myb = 2 * w + bsub;
            const bool act = (lane < 24) && (myb < nb);
            float cel = 0.f;
            bool  cor = false;
            if (act) {
                const float* p = p0 + lane * 33;
                float m0 = -1e30f, m1 = -1e30f, m2 = -1e30f, m3 = -1e30f;
                float s0 = 0.f, s1 = 0.f, s2 = 0.f, s3 = 0.f;
                #pragma unroll
                for (int i = 0; i < 32; i += 4) {
                    float a = p[i], bb2 = p[i+1], c = p[i+2], d = p[i+3];
                    m0 = fmaxf(m0, a);  m1 = fmaxf(m1, bb2);
                    m2 = fmaxf(m2, c);  m3 = fmaxf(m3, d);
                    s0 += __expf(a);  s1 += __expf(bb2);
                    s2 += __expf(c);  s3 += __expf(d);
                }
                const float e32 = p[32];
                const float m = fmaxf(fmaxf(fmaxf(m0, m1), fmaxf(m2, m3)), e32);
                const float s = (s0 + s1) + (s2 + s3) + __expf(e32);
                const float pt = p[pre];             // pre in 0..32 when act
                cor = (pt == m);       // ties measure-zero for random logits
                cel = (pre == 32) ? 0.f : (__logf(s) - pt);
            }
            const unsigned bal = __ballot_sync(FULLM, cor);
            if (act) {
                const unsigned m12 = (bal >> (bsub * 12)) & 0xFFFu;
                const int mi = (m12 == 0xFFFu) ? 0 : (__ffs((int)~m12) - 1);
                const bool ok = (m12 >> jj) & 1u;
                accC += ok ? cel * cwj  : 0.f;
                accE += ok ? 0.f        : cel * cwj1;
                accP += (jj < mi) ? cel * cont.v[mi] : 0.f;
            }
        } else {
            // ---- mask: my slice = 32 rows at byte off w*4224 ----
            if (w * 32 + lane < nr) {
                const float* p = (const float*)(shm + b * BUFB + w * 4224)
                                 + lane * 33;
                float s0 = 0.f, s1 = 0.f, s2 = 0.f, s3 = 0.f;
                #pragma unroll
                for (int i = 0; i < 32; i += 4) {
                    s0 += __expf(p[i]);   s1 += __expf(p[i+1]);
                    s2 += __expf(p[i+2]); s3 += __expf(p[i+3]);
                }
                const float s = (s0 + s1) + (s2 + s3) + __expf(p[32]);
                const int tc = min(max(pre, 0), 32);
                if (pre != -100) {
                    accS += __logf(s) - p[tc];
                    accV += 1.f;
                }
            }
        }
        __syncwarp();                                // warp's reads done
        if (lane == 0) mbar_arrive(mbE0 + b * 8);    // release this warp's reads

        // Producer: refill buffer b for tile u+2g once all 8 warps emptied it.
        if (tid == 0 && u + 2 * g < NT) {
            mbar_wait(mbE0 + b * 8, par);            // acquire consumers' reads
            fill(u + 2 * g, b);
        }
    }

    // ---------------- block reduction -> global atomics ----------------
    double d0 = warp_dsum((double)accS);
    double d1 = warp_dsum((double)accV);
    double d2 = warp_dsum((double)accC);
    double d3 = warp_dsum((double)accE);
    double d4 = warp_dsum((double)accP);
    if (lane == 0) {
        shred[w] = d0; shred[WPB + w] = d1; shred[2*WPB + w] = d2;
        shred[3*WPB + w] = d3; shred[4*WPB + w] = d4;
    }
    __syncthreads();
    if (tid == 0) {
        double a0 = 0, a1 = 0, a2 = 0, a3 = 0, a4 = 0;
        #pragma unroll
        for (int i = 0; i < WPB; i++) {
            a0 += shred[i];          a1 += shred[WPB + i];
            a2 += shred[2*WPB + i];  a3 += shred[3*WPB + i];
            a4 += shred[4*WPB + i];
        }
        atomicAdd(&g_acc[0], a0);
        atomicAdd(&g_acc[1], a1);
        atomicAdd(&g_acc[2], a2);
        atomicAdd(&g_acc[3], a3);
        atomicAdd(&g_acc[4], a4);
        __threadfence();
        unsigned done = atomicAdd(&g_done, 1u);
        if (done == gridDim.x - 1) {
            // last block: read-and-zero (deterministic across graph replays)
            double s0 = __longlong_as_double(atomicExch((unsigned long long*)&g_acc[0], 0ull));
            double s1 = __longlong_as_double(atomicExch((unsigned long long*)&g_acc[1], 0ull));
            double s2 = __longlong_as_double(atomicExch((unsigned long long*)&g_acc[2], 0ull));
            double s3 = __longlong_as_double(atomicExch((unsigned long long*)&g_acc[3], 0ull));
            double s4 = __longlong_as_double(atomicExch((unsigned long long*)&g_acc[4], 0ull));
            atomicExch(&g_done, 0u);

            const double den = (double)B * 12.0;
            double mask_loss = s0 / fmax(s1, 1.0);
            double pl = s4 / den, cl = s2 / den, el = s3 / den;
            double gl = pl + cl + el;
            double L[4] = { gl, mask_loss, (double)aux[0], (double)tok[0] };
            double wsum = 0.0, prod = 1.0;
            #pragma unroll
            for (int i = 0; i < 4; i++) {
                double sg = (double)sigma[i];
                wsum += 0.5 * L[i] / (sg * sg);
                prod *= sg;
            }
            wsum += log(prod);
            out[0] = (float)wsum;
            out[1] = (float)pl;
            out[2] = (float)cl;
            out[3] = (float)el;
            out[4] = (float)mask_loss;
        }
    }
}

extern "C" void kernel_launch(void* const* d_in, const int* in_sizes, int n_in,
                              void* d_out, int out_size) {
    (void)n_in; (void)out_size;
    const float* geo   = (const float*)d_in[0];   // (B, 12, 33) f32
    const float* mgo   = (const float*)d_in[1];   // (B, 13, 33) f32
    const int*   pos   = (const int*)  d_in[2];   // (B, 13) i32
    const int*   gt    = (const int*)  d_in[3];   // (B, 13) i32
    const float* aux   = (const float*)d_in[4];
    const float* tok   = (const float*)d_in[5];
    const float* sigma = (const float*)d_in[6];
    float* out = (float*)d_out;

    const int  B     = (int)((long)in_sizes[0] / 396);
    const long nrows = (long)in_sizes[1] / 33;    // B * 13
    const long NTg   = ((long)B + GEO_BATCHES - 1) / GEO_BATCHES;
    const long NTm   = (nrows + MASK_ROWS - 1) / MASK_ROWS;
    const long NT    = NTg + NTm;

    // CONT_REWARDS closed-form geometric series == reference's Riemann sum
    ContTab cont;
    cont.v[0] = 0.0f;
    for (int k = 1; k <= 12; k++) {
        double b = (double)k;
        double r = pow(0.8, b / 1999.0);
        double integral = (b / 2000.0) * (1.0 - pow(r, 2000.0)) / (1.0 - r);
        cont.v[k] = (float)(1.0 / integral);
    }

    const int dyn_smem = NBUF * BUFB;             // 67584 B double buffer
    cudaFuncSetAttribute(fused_kernel,
                         cudaFuncAttributeMaxDynamicSharedMemorySize, dyn_smem);
    fused_kernel<<<GRID, TPB, dyn_smem>>>(geo, pos, mgo, gt, aux, tok, sigma, out,
                                          B, nrows, NTg, NT, cont);
}